// round 2
// baseline (speedup 1.0000x reference)
#include <cuda_runtime.h>

// ClosebyValuationFunction:
//   dis_x = |z1[:,4] - z2[:,4]|, dis_y = |z1[:,5] - z2[:,5]|
//   out = (dis_x < 2.0 && dis_y <= 0.1) ? 0.99 : 0.01
//
// B = out_size rows of D=6 floats. Cols 4,5 of row i live at float offset
// 6i+4 = an 8-byte-aligned float2 (index 3i+2 in float2 space).
// DRAM-bound: lcm(24B row, 32B sector) = 96B; the needed float2 windows
// touch every sector, so minimal DRAM traffic is the FULL 2*B*24 read
// + B*4 write (~436 MB) — the gather is already traffic-optimal.

__global__ __launch_bounds__(256)
void closeby_kernel(const float2* __restrict__ z1,
                    const float2* __restrict__ z2,
                    float* __restrict__ out,
                    int n)
{
    int i = blockIdx.x * blockDim.x + threadIdx.x;
    if (i < n) {
        int idx = 3 * i + 2;            // float2 index of (col4, col5) in row i
        float2 a = __ldg(&z1[idx]);
        float2 b = __ldg(&z2[idx]);
        float dx = fabsf(a.x - b.x);
        float dy = fabsf(a.y - b.y);
        bool close = (dx < 2.0f) & (dy <= 0.1f);
        out[i] = close ? 0.99f : 0.01f;
    }
}

extern "C" void kernel_launch(void* const* d_in, const int* in_sizes, int n_in,
                              void* d_out, int out_size)
{
    const float2* z1 = (const float2*)d_in[0];
    const float2* z2 = (const float2*)d_in[1];
    float* out = (float*)d_out;
    int n = out_size;                   // B rows (= in_sizes[0] / 6)

    int threads = 256;
    int blocks = (n + threads - 1) / threads;
    closeby_kernel<<<blocks, threads>>>(z1, z2, out, n);
}

// round 4
// speedup vs baseline: 1.0312x; 1.0312x over previous
#include <cuda_runtime.h>

// ClosebyValuationFunction:
//   out[i] = (|z1[i,4]-z2[i,4]| < 2.0 && |z1[i,5]-z2[i,5]| <= 0.1) ? 0.99 : 0.01
//
// Rows are 6 floats (24 B). 4 rows = 96 B = 6 float4. The needed columns
// (4,5 of each row) live only in float4 vectors 1, 2, 4, 5 of each 96 B
// period:
//   row 0: floats 4,5   -> vec1.{x,y}
//   row 1: floats 10,11 -> vec2.{z,w}
//   row 2: floats 16,17 -> vec4.{x,y}
//   row 3: floats 22,23 -> vec5.{z,w}
// vec0/vec3 are never requested; every 32 B sector is still touched by an
// adjacent vector, so DRAM traffic stays at the 436 MB floor while L1
// requests drop by a third. 8x LDG.128 + 1x STG.128 per thread, MLP=8.

__global__ __launch_bounds__(256)
void closeby_quad_kernel(const float4* __restrict__ z1,
                         const float4* __restrict__ z2,
                         float4* __restrict__ out,
                         int nquad)
{
    int t = blockIdx.x * blockDim.x + threadIdx.x;
    if (t >= nquad) return;

    int base = 6 * t;                    // float4 index of this 4-row group

    float4 a1 = __ldcs(&z1[base + 1]);
    float4 a2 = __ldcs(&z1[base + 2]);
    float4 a4 = __ldcs(&z1[base + 4]);
    float4 a5 = __ldcs(&z1[base + 5]);
    float4 b1 = __ldcs(&z2[base + 1]);
    float4 b2 = __ldcs(&z2[base + 2]);
    float4 b4 = __ldcs(&z2[base + 4]);
    float4 b5 = __ldcs(&z2[base + 5]);

    float4 r;
    // row 0: x = vec1.x, y = vec1.y
    r.x = (fabsf(a1.x - b1.x) < 2.0f) & (fabsf(a1.y - b1.y) <= 0.1f) ? 0.99f : 0.01f;
    // row 1: x = vec2.z, y = vec2.w
    r.y = (fabsf(a2.z - b2.z) < 2.0f) & (fabsf(a2.w - b2.w) <= 0.1f) ? 0.99f : 0.01f;
    // row 2: x = vec4.x, y = vec4.y
    r.z = (fabsf(a4.x - b4.x) < 2.0f) & (fabsf(a4.y - b4.y) <= 0.1f) ? 0.99f : 0.01f;
    // row 3: x = vec5.z, y = vec5.w
    r.w = (fabsf(a5.z - b5.z) < 2.0f) & (fabsf(a5.w - b5.w) <= 0.1f) ? 0.99f : 0.01f;

    __stcs(&out[t], r);
}

// Tail: rows not covered by full 4-row groups (none for n = 2^23, but safe).
__global__ void closeby_tail_kernel(const float2* __restrict__ z1,
                                    const float2* __restrict__ z2,
                                    float* __restrict__ out,
                                    int start, int n)
{
    int i = start + blockIdx.x * blockDim.x + threadIdx.x;
    if (i < n) {
        int idx = 3 * i + 2;
        float2 a = __ldg(&z1[idx]);
        float2 b = __ldg(&z2[idx]);
        bool close = (fabsf(a.x - b.x) < 2.0f) & (fabsf(a.y - b.y) <= 0.1f);
        out[i] = close ? 0.99f : 0.01f;
    }
}

extern "C" void kernel_launch(void* const* d_in, const int* in_sizes, int n_in,
                              void* d_out, int out_size)
{
    int n = out_size;                    // B rows (= in_sizes[0] / 6)
    int nquad = n / 4;

    if (nquad > 0) {
        int threads = 256;
        int blocks = (nquad + threads - 1) / threads;
        closeby_quad_kernel<<<blocks, threads>>>(
            (const float4*)d_in[0], (const float4*)d_in[1],
            (float4*)d_out, nquad);
    }
    int tail_start = nquad * 4;
    int tail = n - tail_start;
    if (tail > 0) {
        closeby_tail_kernel<<<1, 128>>>(
            (const float2*)d_in[0], (const float2*)d_in[1],
            (float*)d_out, tail_start, n);
    }
}